// round 2
// baseline (speedup 1.0000x reference)
#include <cuda_runtime.h>

// LIF forward: X [B, T, N] fp32 -> spikes [B, T, N] fp32
// mem_t = (mem_{t-1} + x_t) * 0.5 ; spike = mem > 1 ; mem = spike ? 0 : mem
// Fixed shape: T=32, N=8192. B derived from input size.
//
// R2: 2 independent columns per thread (quad i and i+half) ->
//     - grid halves to 512 blocks: single wave at >=4 blocks/SM
//     - 2 independent LDG.128 chains per thread: doubles MLP
//     __launch_bounds__(256,5) caps regs at 51 so occupancy stays >=5 blocks/SM.

#define T_STEPS 32
#define N_DIM   8192
#define N4      (N_DIM / 4)   // 2048 float4 per row

__global__ __launch_bounds__(256, 5)
void lif_kernel2(const float4* __restrict__ X, float4* __restrict__ out,
                 int half_quads) {
    int idx = blockIdx.x * blockDim.x + threadIdx.x;
    if (idx >= half_quads) return;

    // column A: quad idx ; column B: quad idx + half_quads
    int ia = idx;
    int ib = idx + half_quads;

    int ba = ia / N4;  int na = ia - ba * N4;
    int bb = ib / N4;  int nb = ib - bb * N4;

    const float4* __restrict__ xa = X   + (size_t)ba * (T_STEPS * N4) + na;
    float4* __restrict__       oa = out + (size_t)ba * (T_STEPS * N4) + na;
    const float4* __restrict__ xb = X   + (size_t)bb * (T_STEPS * N4) + nb;
    float4* __restrict__       ob = out + (size_t)bb * (T_STEPS * N4) + nb;

    float ax = 0.f, ay = 0.f, az = 0.f, aw = 0.f;
    float bx = 0.f, by = 0.f, bz = 0.f, bw = 0.f;

    #pragma unroll 4
    for (int t = 0; t < T_STEPS; t++) {
        float4 u = xa[(size_t)t * N4];
        float4 v = xb[(size_t)t * N4];

        ax = (ax + u.x) * 0.5f;  ay = (ay + u.y) * 0.5f;
        az = (az + u.z) * 0.5f;  aw = (aw + u.w) * 0.5f;
        bx = (bx + v.x) * 0.5f;  by = (by + v.y) * 0.5f;
        bz = (bz + v.z) * 0.5f;  bw = (bw + v.w) * 0.5f;

        float4 sa, sb;
        sa.x = (ax > 1.0f) ? 1.0f : 0.0f;
        sa.y = (ay > 1.0f) ? 1.0f : 0.0f;
        sa.z = (az > 1.0f) ? 1.0f : 0.0f;
        sa.w = (aw > 1.0f) ? 1.0f : 0.0f;
        sb.x = (bx > 1.0f) ? 1.0f : 0.0f;
        sb.y = (by > 1.0f) ? 1.0f : 0.0f;
        sb.z = (bz > 1.0f) ? 1.0f : 0.0f;
        sb.w = (bw > 1.0f) ? 1.0f : 0.0f;

        ax = (sa.x > 0.f) ? 0.0f : ax;  ay = (sa.y > 0.f) ? 0.0f : ay;
        az = (sa.z > 0.f) ? 0.0f : az;  aw = (sa.w > 0.f) ? 0.0f : aw;
        bx = (sb.x > 0.f) ? 0.0f : bx;  by = (sb.y > 0.f) ? 0.0f : by;
        bz = (sb.z > 0.f) ? 0.0f : bz;  bw = (sb.w > 0.f) ? 0.0f : bw;

        oa[(size_t)t * N4] = sa;
        ob[(size_t)t * N4] = sb;
    }
}

extern "C" void kernel_launch(void* const* d_in, const int* in_sizes, int n_in,
                              void* d_out, int out_size) {
    const float4* X = (const float4*)d_in[0];
    float4* out = (float4*)d_out;

    int total_elems = in_sizes[0];                  // B*T*N
    int B = total_elems / (T_STEPS * N_DIM);
    int total_quads = B * N4;
    int half_quads = total_quads / 2;               // 2 columns per thread

    int threads = 256;
    int blocks = (half_quads + threads - 1) / threads;
    lif_kernel2<<<blocks, threads>>>(X, out, half_quads);
}